// round 1
// baseline (speedup 1.0000x reference)
#include <cuda_runtime.h>
#include <math.h>
#include <stdint.h>

#define C_IN   256
#define C_B    64
#define K_TAP  27
#define N_MAX  200000
#define BN_EPS 1e-3f

// ---------------- scratch (device globals; no allocation) ----------------
__device__ float g_h1[(size_t)N_MAX * C_B];   // conv1x1a raw -> activated in place
__device__ float g_h2[(size_t)N_MAX * C_B];   // octree conv raw
__device__ float g_h3[(size_t)N_MAX * C_IN];  // conv1x1b raw

__device__ float g_sum1[C_B],  g_sq1[C_B],  g_a1[C_B],  g_c1[C_B];
__device__ float g_sum2[C_B],  g_sq2[C_B],  g_a2[C_B],  g_c2[C_B];
__device__ float g_sum3[C_IN], g_sq3[C_IN], g_a3[C_IN], g_c3[C_IN];

__device__ __forceinline__ float gelu_exact(float x) {
    return 0.5f * x * (1.0f + erff(x * 0.70710678118654752440f));
}

// ---------------- stats reset ----------------
__global__ void zero_stats_kernel() {
    int t = threadIdx.x;
    if (t < C_B)  { g_sum1[t] = 0.f; g_sq1[t] = 0.f; g_sum2[t] = 0.f; g_sq2[t] = 0.f; }
    if (t < C_IN) { g_sum3[t] = 0.f; g_sq3[t] = 0.f; }
}

// ---------------- GEMM1: h1 = data[N,256] @ w1[256,64] ----------------
// 64 rows x 64 cols per block, K chunked by 32. 256 threads, 4x4 micro-tile.
__global__ void gemm1_kernel(const float* __restrict__ data,
                             const float* __restrict__ w1) {
    __shared__ float sA[64][36];   // [row][k] padded
    __shared__ float sB[32][64];   // [k][col]
    const int tid = threadIdx.x;
    const int tx = tid & 15, ty = tid >> 4;
    const int row0 = blockIdx.x * 64;

    const int lr = tid >> 2;            // 0..63 row
    const int lk = (tid & 3) * 8;       // 0..24 k-offset
    const int br = tid >> 3;            // 0..31 k-row for B
    const int bc = (tid & 7) * 8;       // col offset for B

    float acc[4][4] = {};

    for (int kb = 0; kb < C_IN; kb += 32) {
        const float4* ap = (const float4*)(data + (size_t)(row0 + lr) * C_IN + kb + lk);
        float4 a0 = ap[0], a1 = ap[1];
        *(float4*)&sA[lr][lk]     = a0;
        *(float4*)&sA[lr][lk + 4] = a1;

        const float4* bp = (const float4*)(w1 + (size_t)(kb + br) * C_B + bc);
        float4 b0 = bp[0], b1 = bp[1];
        *(float4*)&sB[br][bc]     = b0;
        *(float4*)&sB[br][bc + 4] = b1;
        __syncthreads();

        #pragma unroll
        for (int kk = 0; kk < 32; kk += 4) {
            float4 av[4];
            #pragma unroll
            for (int i = 0; i < 4; i++) av[i] = *(const float4*)&sA[ty * 4 + i][kk];
            #pragma unroll
            for (int u = 0; u < 4; u++) {
                float4 w = *(const float4*)&sB[kk + u][tx * 4];
                #pragma unroll
                for (int i = 0; i < 4; i++) {
                    float a = (&av[i].x)[u];
                    acc[i][0] = fmaf(a, w.x, acc[i][0]);
                    acc[i][1] = fmaf(a, w.y, acc[i][1]);
                    acc[i][2] = fmaf(a, w.z, acc[i][2]);
                    acc[i][3] = fmaf(a, w.w, acc[i][3]);
                }
            }
        }
        __syncthreads();
    }

    #pragma unroll
    for (int i = 0; i < 4; i++) {
        *(float4*)&g_h1[(size_t)(row0 + ty * 4 + i) * C_B + tx * 4] =
            make_float4(acc[i][0], acc[i][1], acc[i][2], acc[i][3]);
    }
}

// ---------------- per-channel stats (sum, sumsq) ----------------
template<int CC>
__device__ __forceinline__ void stats_body(const float* __restrict__ x, int n,
                                           float* __restrict__ sums,
                                           float* __restrict__ sqs) {
    __shared__ float sm[256], qm[256];
    const int tid = threadIdx.x;
    const int col = tid % CC;
    const int rid = tid / CC;
    const int rpt = 256 / CC;

    long long rows_per_blk = (n + gridDim.x - 1) / gridDim.x;
    long long r0 = (long long)blockIdx.x * rows_per_blk;
    long long r1 = r0 + rows_per_blk; if (r1 > n) r1 = n;

    float s = 0.f, q = 0.f;
    for (long long r = r0 + rid; r < r1; r += rpt) {
        float v = x[r * CC + col];
        s += v; q += v * v;
    }
    sm[tid] = s; qm[tid] = q;
    __syncthreads();
    for (int off = 128; off >= CC; off >>= 1) {
        if (tid < off) { sm[tid] += sm[tid + off]; qm[tid] += qm[tid + off]; }
        __syncthreads();
    }
    if (tid < CC) {
        atomicAdd(&sums[tid], sm[tid]);
        atomicAdd(&sqs[tid],  qm[tid]);
    }
}

__global__ void stats1_kernel(int n) { stats_body<C_B >(g_h1, n, g_sum1, g_sq1); }
__global__ void stats2_kernel(int n) { stats_body<C_B >(g_h2, n, g_sum2, g_sq2); }
__global__ void stats3_kernel(int n) { stats_body<C_IN>(g_h3, n, g_sum3, g_sq3); }

// ---------------- BN finalize: a = g*rsqrt(var+eps); c = b - mean*a ----------------
__device__ __forceinline__ void bnfin_body(const float* sums, const float* sqs,
                                           const float* __restrict__ g,
                                           const float* __restrict__ b,
                                           float* a, float* c, float inv_n) {
    int t = threadIdx.x;
    float m = sums[t] * inv_n;
    float v = sqs[t] * inv_n - m * m;
    if (v < 0.f) v = 0.f;
    float s = g[t] * rsqrtf(v + BN_EPS);
    a[t] = s;
    c[t] = b[t] - m * s;
}
__global__ void bnfin1_kernel(const float* __restrict__ g, const float* __restrict__ b, float inv_n)
{ bnfin_body(g_sum1, g_sq1, g, b, g_a1, g_c1, inv_n); }
__global__ void bnfin2_kernel(const float* __restrict__ g, const float* __restrict__ b, float inv_n)
{ bnfin_body(g_sum2, g_sq2, g, b, g_a2, g_c2, inv_n); }
__global__ void bnfin3_kernel(const float* __restrict__ g, const float* __restrict__ b, float inv_n)
{ bnfin_body(g_sum3, g_sq3, g, b, g_a3, g_c3, inv_n); }

// ---------------- BN + GELU applied in place to g_h1 ----------------
__global__ void act1_kernel(long long total) {
    long long i = ((long long)blockIdx.x * blockDim.x + threadIdx.x) * 4;
    if (i >= total) return;
    float4 v = *(float4*)&g_h1[i];
    int c = (int)(i & (C_B - 1));
    v.x = gelu_exact(fmaf(g_a1[c],     v.x, g_c1[c]));
    v.y = gelu_exact(fmaf(g_a1[c + 1], v.y, g_c1[c + 1]));
    v.z = gelu_exact(fmaf(g_a1[c + 2], v.z, g_c1[c + 2]));
    v.w = gelu_exact(fmaf(g_a1[c + 3], v.w, g_c1[c + 3]));
    *(float4*)&g_h1[i] = v;
}

// ---------------- Octree conv: h2[n,d] = sum_k sum_c h1[neigh[n,k],c] * w3[k,c,d] ----------------
// Block: 64 rows x 64 cols. Loop over 27 taps; per tap stage gathered rows + w3[k] in smem.
__global__ void octconv_kernel(const int* __restrict__ neigh,
                               const float* __restrict__ w3) {
    __shared__ float sA[64][68];      // gathered rows [row][c] padded
    __shared__ float sW[64][64];      // w3[k] as [c][d]
    __shared__ int   sIdx[K_TAP][64]; // [k][row]

    const int tid = threadIdx.x;
    const int tx = tid & 15, ty = tid >> 4;
    const int row0 = blockIdx.x * 64;

    for (int i = tid; i < 64 * K_TAP; i += 256) {
        int r = i / K_TAP, k = i - r * K_TAP;
        sIdx[k][r] = neigh[(size_t)(row0 + r) * K_TAP + k];
    }

    const int lr = tid >> 2;        // row this thread helps gather
    const int lf = tid & 3;         // which quarter of the row

    float acc[4][4] = {};
    __syncthreads();

    for (int k = 0; k < K_TAP; k++) {
        // gather 64 rows of h1 (256B each) into sA
        {
            int gr = sIdx[k][lr];
            const float4* src = (const float4*)(g_h1 + (size_t)gr * C_B);
            #pragma unroll
            for (int j = 0; j < 4; j++) {
                int f = lf + 4 * j;               // float4 index 0..15
                *(float4*)&sA[lr][f * 4] = src[f];
            }
        }
        // load w3[k] (64x64)
        {
            const float4* wp = (const float4*)(w3 + (size_t)k * (C_B * C_B));
            #pragma unroll
            for (int j = 0; j < 4; j++)
                ((float4*)sW)[tid + 256 * j] = wp[tid + 256 * j];
        }
        __syncthreads();

        #pragma unroll
        for (int c = 0; c < 64; c += 4) {
            float4 av[4];
            #pragma unroll
            for (int i = 0; i < 4; i++) av[i] = *(const float4*)&sA[ty * 4 + i][c];
            #pragma unroll
            for (int u = 0; u < 4; u++) {
                float4 w = *(const float4*)&sW[c + u][tx * 4];
                #pragma unroll
                for (int i = 0; i < 4; i++) {
                    float a = (&av[i].x)[u];
                    acc[i][0] = fmaf(a, w.x, acc[i][0]);
                    acc[i][1] = fmaf(a, w.y, acc[i][1]);
                    acc[i][2] = fmaf(a, w.z, acc[i][2]);
                    acc[i][3] = fmaf(a, w.w, acc[i][3]);
                }
            }
        }
        __syncthreads();
    }

    #pragma unroll
    for (int i = 0; i < 4; i++) {
        *(float4*)&g_h2[(size_t)(row0 + ty * 4 + i) * C_B + tx * 4] =
            make_float4(acc[i][0], acc[i][1], acc[i][2], acc[i][3]);
    }
}

// ---------------- GEMM2: h3 = act2(h2)[N,64] @ w2[64,256], act fused on A load ----------------
// 64 rows x 256 cols per block, K (=64) chunked by 32.
// Column mapping per thread: col = tx*4 + j4*64 (keeps w-loads conflict-free).
__global__ void gemm2_kernel(const float* __restrict__ w2) {
    __shared__ float sA[64][36];    // [row][c] padded
    __shared__ float sB[32][256];   // [c][col]
    const int tid = threadIdx.x;
    const int tx = tid & 15, ty = tid >> 4;
    const int row0 = blockIdx.x * 64;

    float acc[4][16] = {};

    for (int cb = 0; cb < C_B; cb += 32) {
        // stage A chunk with BN2 + GELU applied
        {
            int lr = tid >> 2;
            int cofs = (tid & 3) * 8;
            const float* src = g_h2 + (size_t)(row0 + lr) * C_B + cb + cofs;
            float4 v0 = *(const float4*)(src);
            float4 v1 = *(const float4*)(src + 4);
            int c = cb + cofs;
            v0.x = gelu_exact(fmaf(g_a2[c],     v0.x, g_c2[c]));
            v0.y = gelu_exact(fmaf(g_a2[c + 1], v0.y, g_c2[c + 1]));
            v0.z = gelu_exact(fmaf(g_a2[c + 2], v0.z, g_c2[c + 2]));
            v0.w = gelu_exact(fmaf(g_a2[c + 3], v0.w, g_c2[c + 3]));
            v1.x = gelu_exact(fmaf(g_a2[c + 4], v1.x, g_c2[c + 4]));
            v1.y = gelu_exact(fmaf(g_a2[c + 5], v1.y, g_c2[c + 5]));
            v1.z = gelu_exact(fmaf(g_a2[c + 6], v1.z, g_c2[c + 6]));
            v1.w = gelu_exact(fmaf(g_a2[c + 7], v1.w, g_c2[c + 7]));
            *(float4*)&sA[lr][cofs]     = v0;
            *(float4*)&sA[lr][cofs + 4] = v1;
        }
        // stage B chunk: w2[cb..cb+32][0..256]
        {
            const float4* wp = (const float4*)(w2 + (size_t)cb * C_IN);
            #pragma unroll
            for (int j = 0; j < 8; j++)
                ((float4*)sB)[tid + 256 * j] = wp[tid + 256 * j];
        }
        __syncthreads();

        #pragma unroll
        for (int c = 0; c < 32; c += 4) {
            float4 av[4];
            #pragma unroll
            for (int i = 0; i < 4; i++) av[i] = *(const float4*)&sA[ty * 4 + i][c];
            #pragma unroll
            for (int u = 0; u < 4; u++) {
                #pragma unroll
                for (int j4 = 0; j4 < 4; j4++) {
                    float4 w = *(const float4*)&sB[c + u][tx * 4 + j4 * 64];
                    #pragma unroll
                    for (int i = 0; i < 4; i++) {
                        float a = (&av[i].x)[u];
                        acc[i][j4 * 4 + 0] = fmaf(a, w.x, acc[i][j4 * 4 + 0]);
                        acc[i][j4 * 4 + 1] = fmaf(a, w.y, acc[i][j4 * 4 + 1]);
                        acc[i][j4 * 4 + 2] = fmaf(a, w.z, acc[i][j4 * 4 + 2]);
                        acc[i][j4 * 4 + 3] = fmaf(a, w.w, acc[i][j4 * 4 + 3]);
                    }
                }
            }
        }
        __syncthreads();
    }

    #pragma unroll
    for (int i = 0; i < 4; i++) {
        #pragma unroll
        for (int j4 = 0; j4 < 4; j4++) {
            *(float4*)&g_h3[(size_t)(row0 + ty * 4 + i) * C_IN + tx * 4 + j4 * 64] =
                make_float4(acc[i][j4 * 4 + 0], acc[i][j4 * 4 + 1],
                            acc[i][j4 * 4 + 2], acc[i][j4 * 4 + 3]);
        }
    }
}

// ---------------- epilogue: out = elu(bn3(h3) + data) ----------------
__global__ void final_kernel(const float* __restrict__ data,
                             float* __restrict__ out, long long total) {
    long long i = ((long long)blockIdx.x * blockDim.x + threadIdx.x) * 4;
    if (i >= total) return;
    float4 h = *(const float4*)&g_h3[i];
    float4 d = *(const float4*)&data[i];
    int c = (int)(i & (C_IN - 1));
    float x;
    x = fmaf(g_a3[c],     h.x, g_c3[c]) + d.x; h.x = x > 0.f ? x : expm1f(x);
    x = fmaf(g_a3[c + 1], h.y, g_c3[c + 1]) + d.y; h.y = x > 0.f ? x : expm1f(x);
    x = fmaf(g_a3[c + 2], h.z, g_c3[c + 2]) + d.z; h.z = x > 0.f ? x : expm1f(x);
    x = fmaf(g_a3[c + 3], h.w, g_c3[c + 3]) + d.w; h.w = x > 0.f ? x : expm1f(x);
    *(float4*)&out[i] = h;
}

// ---------------- launch ----------------
extern "C" void kernel_launch(void* const* d_in, const int* in_sizes, int n_in,
                              void* d_out, int out_size) {
    const float* data = (const float*)d_in[0];
    const int*   neigh = (const int*)d_in[1];
    const float* w1 = (const float*)d_in[2];
    const float* g1 = (const float*)d_in[3];
    const float* b1 = (const float*)d_in[4];
    const float* w3 = (const float*)d_in[5];
    const float* g3 = (const float*)d_in[6];
    const float* b3 = (const float*)d_in[7];
    const float* w2 = (const float*)d_in[8];
    const float* g2 = (const float*)d_in[9];
    const float* b2 = (const float*)d_in[10];
    float* out = (float*)d_out;

    const int n = in_sizes[0] / C_IN;           // 200000 (divisible by 64)
    const float inv_n = 1.0f / (float)n;
    const int nblk64 = n / 64;
    const long long tot_b  = (long long)n * C_B;
    const long long tot_c  = (long long)n * C_IN;

    zero_stats_kernel<<<1, 256>>>();

    gemm1_kernel<<<nblk64, 256>>>(data, w1);
    stats1_kernel<<<512, 256>>>(n);
    bnfin1_kernel<<<1, C_B>>>(g1, b1, inv_n);
    act1_kernel<<<(int)((tot_b / 4 + 255) / 256), 256>>>(tot_b);

    octconv_kernel<<<nblk64, 256>>>(neigh, w3);
    stats2_kernel<<<512, 256>>>(n);
    bnfin2_kernel<<<1, C_B>>>(g3, b3, inv_n);

    gemm2_kernel<<<nblk64, 256>>>(w2);
    stats3_kernel<<<512, 256>>>(n);
    bnfin3_kernel<<<1, C_IN>>>(g2, b2, inv_n);

    final_kernel<<<(int)((tot_c / 4 + 255) / 256), 256>>>(data, out, tot_c);
}